// round 7
// baseline (speedup 1.0000x reference)
#include <cuda_runtime.h>
#include <cstdint>

#define B  8
#define N  4096
#define F  128
#define GS 1024

// Scratch
__device__ unsigned int g_keys[B * N];    // monotone-mapped values
__device__ unsigned int g_hist[B * 256];  // top-8-bit histogram (re-zeroed by select_rank)
__device__ int          g_idx[B * GS];    // final top-k indices, jax order

__device__ __forceinline__ unsigned int monot(float v) {
    unsigned int u = __float_as_uint(v);
    return (u & 0x80000000u) ? ~u : (u | 0x80000000u); // bigger float -> bigger uint
}

// ---------------------------------------------------------------------------
// K1: chip-wide extract + per-batch 256-bin histogram of the top 8 key bits.
// g_hist zero on entry (module zero-init; select_rank re-zeroes each run).
// ---------------------------------------------------------------------------
__global__ __launch_bounds__(256) void extract_hist_kernel(const float* __restrict__ x)
{
    __shared__ unsigned int h[256];
    const int tid = threadIdx.x;
    h[tid] = 0;
    __syncthreads();

    const int i = blockIdx.x * 256 + tid;   // 0 .. B*N-1
    const int b = i >> 12;
    unsigned int u = monot(__ldcs(&x[(size_t)i * F + (F - 1)]));
    g_keys[i] = u;
    atomicAdd(&h[u >> 24], 1u);
    __syncthreads();

    unsigned int c = h[tid];
    if (c) atomicAdd(&g_hist[b * 256 + tid], c);
}

// ---------------------------------------------------------------------------
// K2: per-batch: threshold bin from histogram, candidate compaction,
// 5-pass radix finish on candidates, exact top-GS compaction, fused
// rank-by-count -> ordered g_idx.
// composite = (u << 12) | (4095 - i): larger == earlier in jax order.
// ---------------------------------------------------------------------------
__device__ __forceinline__ void scan_hist(const unsigned int* hist, unsigned int need,
                                          unsigned int* s_bin, unsigned int* s_above)
{
    const int tid = threadIdx.x;
    if (tid < 32) {
        unsigned int sum = 0;
        #pragma unroll
        for (int j = 0; j < 8; ++j) sum += hist[tid * 8 + j];
        unsigned int acc = sum;
        #pragma unroll
        for (int off = 1; off < 32; off <<= 1) {
            unsigned int t = __shfl_down_sync(0xFFFFFFFFu, acc, off);
            if (tid + off < 32) acc += t;
        }
        unsigned int running = acc - sum;      // strictly above my 8-bin group
        #pragma unroll
        for (int j = 7; j >= 0; --j) {
            unsigned int c = hist[tid * 8 + j];
            if (running < need && need <= running + c) {
                *s_bin = (unsigned int)(tid * 8 + j);
                *s_above = running;
            }
            running += c;
        }
    }
}

__global__ __launch_bounds__(1024) void select_rank_kernel()
{
    __shared__ unsigned long long cand[N];                       // 32 KB
    __shared__ __align__(16) unsigned long long ssel[GS];        // 8 KB
    __shared__ unsigned int hist[256];
    __shared__ unsigned int s_bin, s_above, s_m, s_cnt;

    const int b   = blockIdx.x;
    const int tid = threadIdx.x;

    if (tid < 256) { hist[tid] = g_hist[b * 256 + tid]; g_hist[b * 256 + tid] = 0; }
    if (tid == 0) { s_m = 0; s_cnt = 0; }
    __syncthreads();

    scan_hist(hist, GS, &s_bin, &s_above);
    __syncthreads();
    const unsigned int bin1 = s_bin;
    unsigned int need = GS - s_above;

    unsigned long long comp[4];
    #pragma unroll
    for (int l = 0; l < 4; ++l) {
        int i = l * 1024 + tid;
        unsigned int u = g_keys[b * N + i];
        comp[l] = ((unsigned long long)u << 12) | (unsigned int)(N - 1 - i);
        if ((u >> 24) == bin1) {
            unsigned int p = atomicAdd(&s_m, 1u);
            cand[p] = comp[l];
        }
    }
    __syncthreads();
    const unsigned int m = s_m;

    unsigned long long prefix = (unsigned long long)bin1 << 36;
    unsigned long long pmask  = 0xFFull << 36;

    #pragma unroll
    for (int pass = 0; pass < 5; ++pass) {
        const int          shift = (pass < 4) ? (28 - 8 * pass) : 0;
        const unsigned int dmask = (pass < 4) ? 0xFFu : 0xFu;

        if (tid < 256) hist[tid] = 0;
        __syncthreads();
        for (unsigned int idx = tid; idx < m; idx += 1024) {
            unsigned long long k = cand[idx];
            if ((k & pmask) == prefix)
                atomicAdd(&hist[(unsigned int)(k >> shift) & dmask], 1u);
        }
        __syncthreads();
        scan_hist(hist, need, &s_bin, &s_above);
        __syncthreads();
        prefix |= ((unsigned long long)s_bin) << shift;
        pmask  |= ((unsigned long long)dmask) << shift;
        need   -= s_above;
        __syncthreads();
    }

    #pragma unroll
    for (int l = 0; l < 4; ++l) {
        if (comp[l] >= prefix) {
            unsigned int p = atomicAdd(&s_cnt, 1u);
            ssel[p] = comp[l];
        }
    }
    __syncthreads();

    const unsigned long long mine = ssel[tid];
    const ulonglong2* p2 = (const ulonglong2*)ssel;
    int rank = 0;
    #pragma unroll 4
    for (int j = 0; j < GS / 2; ++j) {
        ulonglong2 v = p2[j];
        rank += (v.x > mine) + (v.y > mine);
    }
    g_idx[b * GS + rank] = (N - 1) - (int)(mine & 0xFFFull);
}

// ---------------------------------------------------------------------------
// K3 (R3-proven shape): one CTA per output row (b, i).
//   - coalesced float4 streaming load of A[b, idx[i], :] (16KB) into smem
//   - smem gather of 1024 selected columns -> At2 row (streaming stores)
//   - warp 0 copies x[b, idx[i], :] (512B) -> xg row
// ---------------------------------------------------------------------------
__global__ __launch_bounds__(512) void gather_kernel(const float* __restrict__ A,
                                                     const float* __restrict__ x,
                                                     float* __restrict__ out)
{
    __shared__ float row[N];        // 16 KB
    __shared__ int   sidx[GS];      // 4 KB

    const int bi  = blockIdx.x;
    const int b   = bi >> 10;
    const int i   = bi & (GS - 1);
    const int tid = threadIdx.x;

    const int ri = g_idx[b * GS + i];

    // Coalesced streaming load of the full A row (1024 float4)
    const float4* arow = (const float4*)(A + ((size_t)b * N + ri) * N);
    float4* rowv = (float4*)row;
    #pragma unroll
    for (int t = tid; t < N / 4; t += 512) rowv[t] = __ldcs(&arow[t]);

    // Cache column indices
    #pragma unroll
    for (int t = tid; t < GS; t += 512) sidx[t] = g_idx[b * GS + t];

    // xg row copy: 32 float4 by warp 0
    if (tid < F / 4) {
        const float4* xrow = (const float4*)(x + ((size_t)b * N + ri) * F);
        float4* xgrow = (float4*)(out + (size_t)B * GS * GS
                                      + ((size_t)b * GS + i) * F);
        __stcs(&xgrow[tid], __ldcs(&xrow[tid]));
    }

    __syncthreads();

    // Gather selected columns -> At2 row (coalesced streaming stores)
    float* orow = out + ((size_t)b * GS + i) * GS;
    #pragma unroll
    for (int t = tid; t < GS; t += 512) __stcs(&orow[t], row[sidx[t]]);
}

// ---------------------------------------------------------------------------
extern "C" void kernel_launch(void* const* d_in, const int* in_sizes, int n_in,
                              void* d_out, int out_size)
{
    const float* A = (const float*)d_in[0];  // (8,4096,4096) f32
    const float* x = (const float*)d_in[1];  // (8,4096,128)  f32
    float* out = (float*)d_out;              // At2 (8,1024,1024) ++ xg (8,1024,128)

    extract_hist_kernel<<<(B * N) / 256, 256>>>(x);
    select_rank_kernel<<<B, 1024>>>();
    gather_kernel<<<B * GS, 512>>>(A, x, out);
}

// round 8
// speedup vs baseline: 1.2941x; 1.2941x over previous
#include <cuda_runtime.h>
#include <cstdint>

#define B  8
#define N  4096
#define F  128
#define GS 1024

// Scratch
__device__ unsigned int       g_keys[B * N];   // monotone-mapped values
__device__ unsigned int       g_hist[B * 256]; // top-8-bit histogram (re-zeroed by select)
__device__ unsigned long long g_sel[B * GS];   // selected composites, unordered
__device__ int                g_idx[B * GS];   // final top-k indices, jax order

__device__ __forceinline__ unsigned int monot(float v) {
    unsigned int u = __float_as_uint(v);
    return (u & 0x80000000u) ? ~u : (u | 0x80000000u); // bigger float -> bigger uint
}

// ---------------------------------------------------------------------------
// K1: chip-wide extract + per-batch 256-bin histogram of the top 8 key bits.
// g_hist zero on entry (module zero-init; select_kernel re-zeroes each run).
// ---------------------------------------------------------------------------
__global__ __launch_bounds__(256) void extract_hist_kernel(const float* __restrict__ x)
{
    __shared__ unsigned int h[256];
    const int tid = threadIdx.x;
    h[tid] = 0;
    __syncthreads();

    const int i = blockIdx.x * 256 + tid;   // 0 .. B*N-1
    const int b = i >> 12;
    unsigned int u = monot(__ldcs(&x[(size_t)i * F + (F - 1)]));
    g_keys[i] = u;
    atomicAdd(&h[u >> 24], 1u);
    __syncthreads();

    unsigned int c = h[tid];
    if (c) atomicAdd(&g_hist[b * 256 + tid], c);
}

// ---------------------------------------------------------------------------
// K2: per-batch threshold + compaction ONLY (cheap; ~2us on 8 CTAs).
// composite = (u << 12) | (4095 - i): larger == earlier in jax order.
// ---------------------------------------------------------------------------
__device__ __forceinline__ void scan_hist(const unsigned int* hist, unsigned int need,
                                          unsigned int* s_bin, unsigned int* s_above)
{
    const int tid = threadIdx.x;
    if (tid < 32) {
        unsigned int sum = 0;
        #pragma unroll
        for (int j = 0; j < 8; ++j) sum += hist[tid * 8 + j];
        unsigned int acc = sum;
        #pragma unroll
        for (int off = 1; off < 32; off <<= 1) {
            unsigned int t = __shfl_down_sync(0xFFFFFFFFu, acc, off);
            if (tid + off < 32) acc += t;
        }
        unsigned int running = acc - sum;      // strictly above my 8-bin group
        #pragma unroll
        for (int j = 7; j >= 0; --j) {
            unsigned int c = hist[tid * 8 + j];
            if (running < need && need <= running + c) {
                *s_bin = (unsigned int)(tid * 8 + j);
                *s_above = running;
            }
            running += c;
        }
    }
}

__global__ __launch_bounds__(1024) void select_kernel()
{
    __shared__ unsigned long long cand[N];      // 32 KB
    __shared__ unsigned int hist[256];
    __shared__ unsigned int s_bin, s_above, s_m, s_cnt;

    const int b   = blockIdx.x;
    const int tid = threadIdx.x;

    if (tid < 256) { hist[tid] = g_hist[b * 256 + tid]; g_hist[b * 256 + tid] = 0; }
    if (tid == 0) { s_m = 0; s_cnt = 0; }
    __syncthreads();

    scan_hist(hist, GS, &s_bin, &s_above);
    __syncthreads();
    const unsigned int bin1 = s_bin;
    unsigned int need = GS - s_above;

    unsigned long long comp[4];
    #pragma unroll
    for (int l = 0; l < 4; ++l) {
        int i = l * 1024 + tid;
        unsigned int u = g_keys[b * N + i];
        comp[l] = ((unsigned long long)u << 12) | (unsigned int)(N - 1 - i);
        if ((u >> 24) == bin1) {
            unsigned int p = atomicAdd(&s_m, 1u);
            cand[p] = comp[l];
        }
    }
    __syncthreads();
    const unsigned int m = s_m;

    unsigned long long prefix = (unsigned long long)bin1 << 36;
    unsigned long long pmask  = 0xFFull << 36;

    #pragma unroll
    for (int pass = 0; pass < 5; ++pass) {
        const int          shift = (pass < 4) ? (28 - 8 * pass) : 0;
        const unsigned int dmask = (pass < 4) ? 0xFFu : 0xFu;

        if (tid < 256) hist[tid] = 0;
        __syncthreads();
        for (unsigned int idx = tid; idx < m; idx += 1024) {
            unsigned long long k = cand[idx];
            if ((k & pmask) == prefix)
                atomicAdd(&hist[(unsigned int)(k >> shift) & dmask], 1u);
        }
        __syncthreads();
        scan_hist(hist, need, &s_bin, &s_above);
        __syncthreads();
        prefix |= ((unsigned long long)s_bin) << shift;
        pmask  |= ((unsigned long long)dmask) << shift;
        need   -= s_above;
        __syncthreads();
    }
    // prefix == exact GS-th largest composite. Selected: composite >= prefix.

    #pragma unroll
    for (int l = 0; l < 4; ++l) {
        if (comp[l] >= prefix) {
            unsigned int p = atomicAdd(&s_cnt, 1u);
            g_sel[b * GS + p] = comp[l];
        }
    }
}

// ---------------------------------------------------------------------------
// K3 (R3-proven): rank-by-count over 1024 selected keys, 64 CTAs x 128 thr.
// ---------------------------------------------------------------------------
__global__ __launch_bounds__(128) void rank_kernel()
{
    __shared__ unsigned long long sk[GS];  // 8 KB

    const int b   = blockIdx.x >> 3;
    const int c   = blockIdx.x & 7;
    const int tid = threadIdx.x;

    #pragma unroll
    for (int l = 0; l < GS / 128; ++l)
        sk[tid + l * 128] = g_sel[b * GS + tid + l * 128];
    __syncthreads();

    const unsigned long long mine = sk[c * 128 + tid];
    int rank = 0;
    #pragma unroll 8
    for (int j = 0; j < GS; ++j)
        rank += (sk[j] > mine);

    g_idx[b * GS + rank] = (N - 1) - (int)(mine & 0xFFFull);
}

// ---------------------------------------------------------------------------
// K4 (R3-proven): one CTA per output row (b, i).
//   - coalesced float4 streaming load of A[b, idx[i], :] (16KB) into smem
//   - smem gather of 1024 selected columns -> At2 row
//   - warp 0 copies x[b, idx[i], :] (512B) -> xg row
// ---------------------------------------------------------------------------
__global__ __launch_bounds__(512) void gather_kernel(const float* __restrict__ A,
                                                     const float* __restrict__ x,
                                                     float* __restrict__ out)
{
    __shared__ float row[N];        // 16 KB
    __shared__ int   sidx[GS];      // 4 KB

    const int bi  = blockIdx.x;
    const int b   = bi >> 10;
    const int i   = bi & (GS - 1);
    const int tid = threadIdx.x;

    const int ri = g_idx[b * GS + i];

    const float4* arow = (const float4*)(A + ((size_t)b * N + ri) * N);
    float4* rowv = (float4*)row;
    #pragma unroll
    for (int t = tid; t < N / 4; t += 512) rowv[t] = __ldcs(&arow[t]);

    #pragma unroll
    for (int t = tid; t < GS; t += 512) sidx[t] = g_idx[b * GS + t];

    if (tid < F / 4) {
        const float4* xrow = (const float4*)(x + ((size_t)b * N + ri) * F);
        float4* xgrow = (float4*)(out + (size_t)B * GS * GS
                                      + ((size_t)b * GS + i) * F);
        xgrow[tid] = xrow[tid];
    }

    __syncthreads();

    float* orow = out + ((size_t)b * GS + i) * GS;
    #pragma unroll
    for (int t = tid; t < GS; t += 512) orow[t] = row[sidx[t]];
}

// ---------------------------------------------------------------------------
extern "C" void kernel_launch(void* const* d_in, const int* in_sizes, int n_in,
                              void* d_out, int out_size)
{
    const float* A = (const float*)d_in[0];  // (8,4096,4096) f32
    const float* x = (const float*)d_in[1];  // (8,4096,128)  f32
    float* out = (float*)d_out;              // At2 (8,1024,1024) ++ xg (8,1024,128)

    extract_hist_kernel<<<(B * N) / 256, 256>>>(x);
    select_kernel<<<B, 1024>>>();
    rank_kernel<<<B * 8, 128>>>();
    gather_kernel<<<B * GS, 512>>>(A, x, out);
}